// round 3
// baseline (speedup 1.0000x reference)
#include <cuda_runtime.h>
#include <cstdint>
#include <cstddef>

// MeanAggregator on GB300 (sm_103a, but ptxas target is plain sm_103 ->
// tcgen05 unavailable; use legacy tf32 mma.sync).
//
//   out[:, 0:64]   = self_x @ Ws + bs                       (prep kernel)
//   out[:, 64:128] = (adj @ (nx @ Wn)) / max(rowsum(adj),1) + bn
//     -> one tf32 GEMM: D[16384,72] = adj @ B^T
//        B[72,16384] = [ (nx@Wn)^T ; ones ; zeros(7) ]; col 64 of D = deg.

#define NROWS    16384
#define KC       32                      // K per pipeline stage
#define NIT      (NROWS / KC)            // 512
#define NSTAGES  4
#define ASTRIDE  36                      // floats per smem row (32 + 4 pad)
#define A_ROWS   128
#define B_ROWS   72
#define A_ST_BYTES (A_ROWS * ASTRIDE * 4)            // 18432
#define B_ST_BYTES (B_ROWS * ASTRIDE * 4)            // 10368
#define ST_BYTES   (A_ST_BYTES + B_ST_BYTES)         // 28800
#define SMEM_TOTAL (256 + NSTAGES * ST_BYTES)        // 115456

__device__ float g_B[(size_t)B_ROWS * NROWS];        // 4.5 MB static scratch

// ---------------- helpers ----------------

static __device__ __forceinline__ uint32_t smem_u32(const void* p) {
    uint32_t a;
    asm("{ .reg .u64 t; cvta.to.shared.u64 t, %1; cvt.u32.u64 %0, t; }"
        : "=r"(a) : "l"(p));
    return a;
}

static __device__ __forceinline__ void cp16(uint32_t dst, const void* src) {
    asm volatile("cp.async.cg.shared.global [%0], [%1], 16;"
                 :: "r"(dst), "l"(src) : "memory");
}

static __device__ __forceinline__ void mma_tf32(float* d,
                                                uint32_t a0, uint32_t a1,
                                                uint32_t a2, uint32_t a3,
                                                uint32_t b0, uint32_t b1) {
    asm volatile(
        "mma.sync.aligned.m16n8k8.row.col.f32.tf32.tf32.f32 "
        "{%0,%1,%2,%3}, {%4,%5,%6,%7}, {%8,%9}, {%0,%1,%2,%3};"
        : "+f"(d[0]), "+f"(d[1]), "+f"(d[2]), "+f"(d[3])
        : "r"(a0), "r"(a1), "r"(a2), "r"(a3), "r"(b0), "r"(b1));
}

// ---------------- stage loader (cp.async, padded rows) ----------------

static __device__ __forceinline__ void load_stage(char* smem, int slot, int k0,
                                                  int m0, int tid,
                                                  const float* __restrict__ adj) {
    char* base = smem + 256 + slot * ST_BYTES;
#pragma unroll
    for (int i = 0; i < 7; i++) {
        int c = i * 256 + tid;             // 1024 A-chunks + 576 B-chunks of 16B
        if (c < 1024) {
            int row = c >> 3, w = c & 7;
            uint32_t dst = smem_u32(base + row * (ASTRIDE * 4) + w * 16);
            cp16(dst, adj + (size_t)(m0 + row) * NROWS + k0 + w * 4);
        } else if (c < 1600) {
            int cb = c - 1024;
            int row = cb >> 3, w = cb & 7;
            uint32_t dst = smem_u32(base + A_ST_BYTES + row * (ASTRIDE * 4) + w * 16);
            cp16(dst, g_B + (size_t)row * NROWS + k0 + w * 4);
        }
    }
}

// ---------------- main GEMM ----------------

__global__ void __launch_bounds__(256, 1)
gcn_gemm(const float* __restrict__ adj, const float* __restrict__ nbias,
         float* __restrict__ out) {
    extern __shared__ char smem[];
    const int tid  = threadIdx.x;
    const int lane = tid & 31;
    const int warp = tid >> 5;              // 0..7, each owns 16 rows
    const int g    = lane >> 2;             // group id 0..7
    const int tig  = lane & 3;              // thread in group 0..3
    const int m0   = blockIdx.x * 128;

    if (tid < 64) ((float*)smem)[tid] = nbias[tid];

    // prologue: 3 stages in flight
    load_stage(smem, 0, 0,      m0, tid, adj);
    asm volatile("cp.async.commit_group;" ::: "memory");
    load_stage(smem, 1, KC,     m0, tid, adj);
    asm volatile("cp.async.commit_group;" ::: "memory");
    load_stage(smem, 2, 2 * KC, m0, tid, adj);
    asm volatile("cp.async.commit_group;" ::: "memory");

    float acc[36];                          // [n8 tile][4], tile 8 = deg column
#pragma unroll
    for (int i = 0; i < 36; i++) acc[i] = 0.0f;

    for (int it = 0; it < NIT; it++) {
        asm volatile("cp.async.wait_group 2;" ::: "memory");  // stage `it` landed
        __syncthreads();                     // data visible + slot (it-1) free

        const int ld = it + 3;
        if (ld < NIT) load_stage(smem, ld & 3, ld * KC, m0, tid, adj);
        asm volatile("cp.async.commit_group;" ::: "memory");

        const char* base = smem + 256 + (it & 3) * ST_BYTES;
        const uint32_t* Ap = (const uint32_t*)base + (warp * 16 + g) * ASTRIDE + tig;
        const uint32_t* Bp = (const uint32_t*)(base + A_ST_BYTES) + g * ASTRIDE + tig;

#pragma unroll
        for (int kk = 0; kk < 4; kk++) {     // 4 x k8 per stage
            const uint32_t a0 = Ap[kk * 8];
            const uint32_t a1 = Ap[kk * 8 + 8 * ASTRIDE];
            const uint32_t a2 = Ap[kk * 8 + 4];
            const uint32_t a3 = Ap[kk * 8 + 8 * ASTRIDE + 4];
#pragma unroll
            for (int n = 0; n < 9; n++) {
                const uint32_t b0 = Bp[n * 8 * ASTRIDE + kk * 8];
                const uint32_t b1 = Bp[n * 8 * ASTRIDE + kk * 8 + 4];
                mma_tf32(acc + n * 4, a0, a1, a2, a3, b0, b1);
            }
        }
    }

    // ---- epilogue: deg from column 64 (tile 8, even col of tig==0 thread) ----
    const float deg0 = __shfl_sync(0xffffffffu, acc[32], lane & ~3);
    const float deg1 = __shfl_sync(0xffffffffu, acc[34], lane & ~3);
    const float inv0 = 1.0f / fmaxf(deg0, 1.0f);
    const float inv1 = 1.0f / fmaxf(deg1, 1.0f);

    const float* sb = (const float*)smem;    // neighbor bias
    const int r0 = m0 + warp * 16 + g;
    float* o0 = out + (size_t)r0 * 128 + 64;
    float* o1 = out + (size_t)(r0 + 8) * 128 + 64;
#pragma unroll
    for (int n = 0; n < 8; n++) {
        const int col = n * 8 + tig * 2;
        float2 v0, v1;
        v0.x = acc[n * 4 + 0] * inv0 + sb[col];
        v0.y = acc[n * 4 + 1] * inv0 + sb[col + 1];
        v1.x = acc[n * 4 + 2] * inv1 + sb[col];
        v1.y = acc[n * 4 + 3] * inv1 + sb[col + 1];
        *reinterpret_cast<float2*>(o0 + col) = v0;
        *reinterpret_cast<float2*>(o1 + col) = v1;
    }
}

// ---------------- prep: out_self + B matrix (tf32-rounded) ----------------

static __device__ __forceinline__ float to_tf32(float x) {
    uint32_t t;
    asm("cvt.rna.tf32.f32 %0, %1;" : "=r"(t) : "f"(x));
    return __uint_as_float(t);
}

__global__ void __launch_bounds__(128)
gcn_prep(const float* __restrict__ sx, const float* __restrict__ nx,
         const float* __restrict__ Ws, const float* __restrict__ Wn,
         const float* __restrict__ bs, float* __restrict__ out) {
    __shared__ float wsT[64 * 64];
    __shared__ float wnT[64 * 64];
    __shared__ float sbias[64];
    const int tid = threadIdx.x;
    for (int i = tid; i < 4096; i += 128) {
        const int d = i >> 6, n = i & 63;
        wsT[n * 64 + d] = Ws[i];
        wnT[n * 64 + d] = Wn[i];
    }
    if (tid < 64) sbias[tid] = bs[tid];
    __syncthreads();

    const int m = blockIdx.x * 128 + tid;
    {   // out_self = self_x @ Ws + bs  (full fp32)
        float4 x[16];
        const float4* xp = reinterpret_cast<const float4*>(sx + (size_t)m * 64);
#pragma unroll
        for (int i = 0; i < 16; i++) x[i] = xp[i];
        float* op = out + (size_t)m * 128;
        for (int n = 0; n < 64; n++) {
            const float4* w = reinterpret_cast<const float4*>(wsT + n * 64);
            float a = 0.f;
#pragma unroll
            for (int i = 0; i < 16; i++) {
                const float4 wv = w[i];
                a += x[i].x * wv.x + x[i].y * wv.y + x[i].z * wv.z + x[i].w * wv.w;
            }
            op[n] = a + sbias[n];
        }
    }
    {   // B rows 0..63 = (nx@Wn)^T (tf32-rounded); row 64 = ones; 65..71 = 0
        float4 x[16];
        const float4* xp = reinterpret_cast<const float4*>(nx + (size_t)m * 64);
#pragma unroll
        for (int i = 0; i < 16; i++) x[i] = xp[i];
        for (int n = 0; n < 64; n++) {
            const float4* w = reinterpret_cast<const float4*>(wnT + n * 64);
            float a = 0.f;
#pragma unroll
            for (int i = 0; i < 16; i++) {
                const float4 wv = w[i];
                a += x[i].x * wv.x + x[i].y * wv.y + x[i].z * wv.z + x[i].w * wv.w;
            }
            g_B[(size_t)n * NROWS + m] = to_tf32(a);
        }
        g_B[(size_t)64 * NROWS + m] = 1.0f;
#pragma unroll
        for (int r = 65; r < 72; r++) g_B[(size_t)r * NROWS + m] = 0.0f;
    }
}

// ---------------- launch ----------------

extern "C" void kernel_launch(void* const* d_in, const int* in_sizes, int n_in,
                              void* d_out, int out_size) {
    const float* sx  = (const float*)d_in[0];
    const float* nx  = (const float*)d_in[1];
    const float* adj = (const float*)d_in[2];
    const float* Ws  = (const float*)d_in[3];
    const float* Wn  = (const float*)d_in[4];
    const float* bs  = (const float*)d_in[5];
    const float* bn  = (const float*)d_in[6];
    float* out = (float*)d_out;

    cudaFuncSetAttribute(gcn_gemm, cudaFuncAttributeMaxDynamicSharedMemorySize,
                         SMEM_TOTAL);
    gcn_prep<<<NROWS / 128, 128>>>(sx, nx, Ws, Wn, bs, out);
    gcn_gemm<<<NROWS / 128, 256, SMEM_TOTAL>>>(adj, bn, out);
}

// round 4
// speedup vs baseline: 1.0035x; 1.0035x over previous
#include <cuda_runtime.h>
#include <cstdint>
#include <cstddef>

// MeanAggregator on GB300 (sm_103a; ptxas target sm_103 -> no tcgen05,
// use legacy tf32 mma.sync m16n8k8).
//
//   out[:, 0:64]   = self_x @ Ws + bs                       (prep kernel)
//   out[:, 64:128] = (adj @ (nx @ Wn)) / max(rowsum(adj),1) + bn
//     -> one tf32 GEMM: D[16384,72] = adj @ B^T
//        B[72,16384] = [ (nx@Wn)^T ; ones ; zeros(7) ]; D col 64 = deg.
//
// GEMM: 128 CTAs x 256 thr. Warp tile 32x40: warp w -> m-strip (w>>1)*32,
// n-half (w&1): tiles {half*32 + 0,8,16,24} plus the deg tile (rows 64..71).

#define NROWS    16384
#define KC       32
#define NIT      (NROWS / KC)            // 512
#define ASTRIDE  36                      // floats per smem row (32 + 4 pad)
#define A_ROWS   128
#define B_ROWS   72
#define A_ST_BYTES (A_ROWS * ASTRIDE * 4)            // 18432
#define B_ST_BYTES (B_ROWS * ASTRIDE * 4)            // 10368
#define ST_BYTES   (A_ST_BYTES + B_ST_BYTES)         // 28800
#define SMEM_TOTAL (256 + 4 * ST_BYTES)              // 115456

__device__ float g_B[(size_t)B_ROWS * NROWS];        // 4.5 MB static scratch

// ---------------- helpers ----------------

static __device__ __forceinline__ uint32_t smem_u32(const void* p) {
    uint32_t a;
    asm("{ .reg .u64 t; cvta.to.shared.u64 t, %1; cvt.u32.u64 %0, t; }"
        : "=r"(a) : "l"(p));
    return a;
}

static __device__ __forceinline__ void cp16(uint32_t dst, const void* src) {
    asm volatile("cp.async.cg.shared.global [%0], [%1], 16;"
                 :: "r"(dst), "l"(src) : "memory");
}

static __device__ __forceinline__ void mma_tf32(float* d,
                                                uint32_t a0, uint32_t a1,
                                                uint32_t a2, uint32_t a3,
                                                uint32_t b0, uint32_t b1) {
    asm volatile(
        "mma.sync.aligned.m16n8k8.row.col.f32.tf32.tf32.f32 "
        "{%0,%1,%2,%3}, {%4,%5,%6,%7}, {%8,%9}, {%0,%1,%2,%3};"
        : "+f"(d[0]), "+f"(d[1]), "+f"(d[2]), "+f"(d[3])
        : "r"(a0), "r"(a1), "r"(a2), "r"(a3), "r"(b0), "r"(b1));
}

// ---------------- stage loader (cp.async, padded rows) ----------------

static __device__ __forceinline__ void load_stage(char* smem, int slot, int k0,
                                                  int m0, int tid,
                                                  const float* __restrict__ adj) {
    char* base = smem + 256 + slot * ST_BYTES;
#pragma unroll
    for (int i = 0; i < 7; i++) {
        int c = i * 256 + tid;             // 1024 A-chunks + 576 B-chunks of 16B
        if (c < 1024) {
            int row = c >> 3, w = c & 7;
            uint32_t dst = smem_u32(base + row * (ASTRIDE * 4) + w * 16);
            cp16(dst, adj + (size_t)(m0 + row) * NROWS + k0 + w * 4);
        } else if (c < 1600) {
            int cb = c - 1024;
            int row = cb >> 3, w = cb & 7;
            uint32_t dst = smem_u32(base + A_ST_BYTES + row * (ASTRIDE * 4) + w * 16);
            cp16(dst, g_B + (size_t)row * NROWS + k0 + w * 4);
        }
    }
}

// ---------------- main GEMM ----------------

__global__ void __launch_bounds__(256, 1)
gcn_gemm(const float* __restrict__ adj, const float* __restrict__ nbias,
         float* __restrict__ out) {
    extern __shared__ char smem[];
    const int tid  = threadIdx.x;
    const int lane = tid & 31;
    const int warp = tid >> 5;
    const int mw   = warp >> 1;             // m-strip 0..3 (32 rows each)
    const int nh   = warp & 1;              // n-half 0/1
    const int rm   = mw * 32;
    const int g    = lane >> 2;
    const int tig  = lane & 3;
    const int m0   = blockIdx.x * 128;

    if (tid < 64) ((float*)smem)[tid] = nbias[tid];

    load_stage(smem, 0, 0,      m0, tid, adj);
    asm volatile("cp.async.commit_group;" ::: "memory");
    load_stage(smem, 1, KC,     m0, tid, adj);
    asm volatile("cp.async.commit_group;" ::: "memory");
    load_stage(smem, 2, 2 * KC, m0, tid, adj);
    asm volatile("cp.async.commit_group;" ::: "memory");

    // B-tile row offsets for this warp: 4 output tiles + deg tile (row 64)
    int toff[5];
#pragma unroll
    for (int nt = 0; nt < 4; nt++) toff[nt] = nh * 32 + nt * 8;
    toff[4] = 64;

    float acc[2][5][4];                     // [m16 tile][n8 tile][frag]
#pragma unroll
    for (int mt = 0; mt < 2; mt++)
#pragma unroll
        for (int nt = 0; nt < 5; nt++)
#pragma unroll
            for (int q = 0; q < 4; q++) acc[mt][nt][q] = 0.0f;

    for (int it = 0; it < NIT; it++) {
        asm volatile("cp.async.wait_group 2;" ::: "memory");
        __syncthreads();

        const int ld = it + 3;
        if (ld < NIT) load_stage(smem, ld & 3, ld * KC, m0, tid, adj);
        asm volatile("cp.async.commit_group;" ::: "memory");

        const char* base = smem + 256 + (it & 3) * ST_BYTES;
        const uint32_t* Ap = (const uint32_t*)base + (rm + g) * ASTRIDE + tig;
        const uint32_t* Bp = (const uint32_t*)(base + A_ST_BYTES) + g * ASTRIDE + tig;

#pragma unroll
        for (int kk = 0; kk < 4; kk++) {
            const int ko = kk * 8;
            const uint32_t a0 = Ap[ko];
            const uint32_t a1 = Ap[ko + 8 * ASTRIDE];
            const uint32_t a2 = Ap[ko + 4];
            const uint32_t a3 = Ap[ko + 8 * ASTRIDE + 4];
            const uint32_t a4 = Ap[ko + 16 * ASTRIDE];
            const uint32_t a5 = Ap[ko + 24 * ASTRIDE];
            const uint32_t a6 = Ap[ko + 16 * ASTRIDE + 4];
            const uint32_t a7 = Ap[ko + 24 * ASTRIDE + 4];
#pragma unroll
            for (int nt = 0; nt < 5; nt++) {
                const uint32_t b0 = Bp[toff[nt] * ASTRIDE + ko];
                const uint32_t b1 = Bp[toff[nt] * ASTRIDE + ko + 4];
                mma_tf32(acc[0][nt], a0, a1, a2, a3, b0, b1);
                mma_tf32(acc[1][nt], a4, a5, a6, a7, b0, b1);
            }
        }
    }

    // ---- epilogue: deg from tile 4 (D col 64, held by tig==0 as c0/c2) ----
    const float* sb = (const float*)smem;   // neighbor bias (cols 0..63)
#pragma unroll
    for (int mt = 0; mt < 2; mt++) {
        const float d0 = __shfl_sync(0xffffffffu, acc[mt][4][0], lane & ~3);
        const float d1 = __shfl_sync(0xffffffffu, acc[mt][4][2], lane & ~3);
        const float inv0 = 1.0f / fmaxf(d0, 1.0f);
        const float inv1 = 1.0f / fmaxf(d1, 1.0f);
        const int r0 = m0 + rm + mt * 16 + g;
        float* o0 = out + (size_t)r0 * 128 + 64;
        float* o1 = out + (size_t)(r0 + 8) * 128 + 64;
#pragma unroll
        for (int nt = 0; nt < 4; nt++) {
            const int dcol = nh * 32 + nt * 8 + tig * 2;
            float2 v0, v1;
            v0.x = acc[mt][nt][0] * inv0 + sb[dcol];
            v0.y = acc[mt][nt][1] * inv0 + sb[dcol + 1];
            v1.x = acc[mt][nt][2] * inv1 + sb[dcol];
            v1.y = acc[mt][nt][3] * inv1 + sb[dcol + 1];
            *reinterpret_cast<float2*>(o0 + dcol) = v0;
            *reinterpret_cast<float2*>(o1 + dcol) = v1;
        }
    }
}

// ---------------- prep: out_self + B matrix (tf32-rounded) ----------------

static __device__ __forceinline__ float to_tf32(float x) {
    uint32_t t;
    asm("cvt.rna.tf32.f32 %0, %1;" : "=r"(t) : "f"(x));
    return __uint_as_float(t);
}

static __device__ __forceinline__ float dot64(const float4* __restrict__ x,
                                              const float4* __restrict__ w) {
    float4 s = make_float4(0.f, 0.f, 0.f, 0.f);
#pragma unroll
    for (int i = 0; i < 16; i++) {
        const float4 wv = w[i];
        s.x = fmaf(x[i].x, wv.x, s.x);
        s.y = fmaf(x[i].y, wv.y, s.y);
        s.z = fmaf(x[i].z, wv.z, s.z);
        s.w = fmaf(x[i].w, wv.w, s.w);
    }
    return (s.x + s.y) + (s.z + s.w);
}

__global__ void __launch_bounds__(128)
gcn_prep(const float* __restrict__ sx, const float* __restrict__ nx,
         const float* __restrict__ Ws, const float* __restrict__ Wn,
         const float* __restrict__ bs, float* __restrict__ out) {
    __shared__ float wsT[64 * 64];
    __shared__ float wnT[64 * 64];
    __shared__ float sbias[64];
    const int tid = threadIdx.x;
    for (int i = tid; i < 4096; i += 128) {
        const int d = i >> 6, n = i & 63;
        wsT[n * 64 + d] = Ws[i];
        wnT[n * 64 + d] = Wn[i];
    }
    if (tid < 64) sbias[tid] = bs[tid];
    __syncthreads();

    const int m = blockIdx.x * 128 + tid;
    {   // out_self = self_x @ Ws + bs  (full fp32)
        float4 x[16];
        const float4* xp = reinterpret_cast<const float4*>(sx + (size_t)m * 64);
#pragma unroll
        for (int i = 0; i < 16; i++) x[i] = xp[i];
        float* op = out + (size_t)m * 128;
        for (int n = 0; n < 64; n++)
            op[n] = dot64(x, reinterpret_cast<const float4*>(wsT + n * 64)) + sbias[n];
    }
    {   // B rows 0..63 = (nx@Wn)^T (tf32-rounded); row 64 = ones; 65..71 = 0
        float4 x[16];
        const float4* xp = reinterpret_cast<const float4*>(nx + (size_t)m * 64);
#pragma unroll
        for (int i = 0; i < 16; i++) x[i] = xp[i];
        for (int n = 0; n < 64; n++)
            g_B[(size_t)n * NROWS + m] =
                to_tf32(dot64(x, reinterpret_cast<const float4*>(wnT + n * 64)));
        g_B[(size_t)64 * NROWS + m] = 1.0f;
#pragma unroll
        for (int r = 65; r < 72; r++) g_B[(size_t)r * NROWS + m] = 0.0f;
    }
}

// ---------------- launch ----------------

extern "C" void kernel_launch(void* const* d_in, const int* in_sizes, int n_in,
                              void* d_out, int out_size) {
    const float* sx  = (const float*)d_in[0];
    const float* nx  = (const float*)d_in[1];
    const float* adj = (const float*)d_in[2];
    const float* Ws  = (const float*)d_in[3];
    const float* Wn  = (const float*)d_in[4];
    const float* bs  = (const float*)d_in[5];
    const float* bn  = (const float*)d_in[6];
    float* out = (float*)d_out;

    cudaFuncSetAttribute(gcn_gemm, cudaFuncAttributeMaxDynamicSharedMemorySize,
                         SMEM_TOTAL);
    gcn_prep<<<NROWS / 128, 128>>>(sx, nx, Ws, Wn, bs, out);
    gcn_gemm<<<NROWS / 128, 256, SMEM_TOTAL>>>(adj, bn, out);
}